// round 14
// baseline (speedup 1.0000x reference)
#include <cuda_runtime.h>
#include <cuda_fp16.h>
#include <cstdint>

#define SLOPE 0.15f

static const int NN = 50000;
static const int NE = 800000;

// ---------------- device scratch ----------------------------------------------
__device__ int    g_deg[NN];
__device__ int    g_rowptr[NN + 1];
__device__ int    g_cursor[NN];
__device__ int    g_csr[NE];
__device__ __half g_xh[(size_t)NN * 128];
__device__ __half g_wt1h[512 * 256];
__device__ __half g_wt2h[512 * 512];
__device__ __half g_wt3h[128 * 256];
__device__ __half g_mean1h[(size_t)NN * 128];
__device__ __half g_h1h[(size_t)NN * 512];
__device__ __half g_c2h[(size_t)NN * 512];    // [z2 | r2]
__device__ __half g_h2h[NN * 256];
__device__ __half g_c3h[NN * 128];            // [z3 | r3]
__device__ __half g_h3h[NN * 64];

__device__ __forceinline__ unsigned sm32(const void* p) {
    return (unsigned)__cvta_generic_to_shared(p);
}

// ---------------- fused prologue: deg count + x->half + weight prep ------------
__global__ void prologue_kernel(
    const int* __restrict__ dst, int* __restrict__ deg, int ne,
    const float* __restrict__ x, int n4x,
    const float* __restrict__ W1l, const float* __restrict__ W1r,
    const float* __restrict__ W2l, const float* __restrict__ W2r,
    const float* __restrict__ W3l, const float* __restrict__ W3r,
    int CB, int XB)
{
    int b = blockIdx.x;
    if (b < CB) {
        int e = (b * 256 + threadIdx.x) * 4;
        if (e + 3 < ne) {
            int4 d = *(const int4*)(dst + e);
            atomicAdd(&deg[d.x], 1);
            atomicAdd(&deg[d.y], 1);
            atomicAdd(&deg[d.z], 1);
            atomicAdd(&deg[d.w], 1);
        } else {
            for (int k = e; k < ne; k++) atomicAdd(&deg[dst[k]], 1);
        }
        return;
    }
    b -= CB;
    if (b < XB) {
        int i = b * 256 + threadIdx.x;
        if (i >= n4x) return;
        float4 v = ((const float4*)x)[i];
        __half2* o = (__half2*)g_xh + (size_t)i * 2;
        o[0] = __float22half2_rn(make_float2(v.x, v.y));
        o[1] = __float22half2_rn(make_float2(v.z, v.w));
        return;
    }
    b -= XB;
    int i = b * 256 + threadIdx.x;
    if (i < 512 * 256) {
        int nn = i >> 8, k = i & 255;
        float v = (k < 128) ? W1l[k * 512 + nn] : W1r[(k - 128) * 512 + nn];
        g_wt1h[i] = __float2half_rn(v);
        return;
    }
    int j = i - 512 * 256;
    if (j < 512 * 512) {
        int nn = j >> 9, k = j & 511;
        float v = (nn < 256) ? W2l[k * 256 + nn] : W2r[k * 256 + (nn - 256)];
        g_wt2h[j] = __float2half_rn(v);
        return;
    }
    int l = j - 512 * 512;
    if (l < 128 * 256) {
        int nn = l >> 8, k = l & 255;
        float v = (nn < 64) ? W3l[k * 64 + nn] : W3r[k * 64 + (nn - 64)];
        g_wt3h[l] = __float2half_rn(v);
    }
}

// ---------------- CSR scan + scatter --------------------------------------------
__global__ void scan_kernel(const int* __restrict__ deg, int* __restrict__ rowptr,
                            int* __restrict__ cursor, int n) {
    __shared__ int part[1024];
    const int t = threadIdx.x;
    const int chunk = (n + 1023) >> 10;
    int lo = t * chunk;
    int hi = lo + chunk; if (hi > n) hi = n;
    int s = 0;
    for (int i = lo; i < hi; i++) s += deg[i];
    part[t] = s;
    __syncthreads();
    for (int off = 1; off < 1024; off <<= 1) {
        int v = (t >= off) ? part[t - off] : 0;
        __syncthreads();
        part[t] += v;
        __syncthreads();
    }
    int base = (t == 0) ? 0 : part[t - 1];
    for (int i = lo; i < hi; i++) {
        rowptr[i] = base; cursor[i] = base;
        base += deg[i];
    }
    if (t == 1023) rowptr[n] = base;
}

__global__ void scatter_kernel(const int* __restrict__ src, const int* __restrict__ dst,
                               int* __restrict__ cursor, int* __restrict__ csr, int ne) {
    int e = (blockIdx.x * blockDim.x + threadIdx.x) * 4;
    if (e + 3 < ne) {
        int4 s = *(const int4*)(src + e);
        int4 d = *(const int4*)(dst + e);
        int p0 = atomicAdd(&cursor[d.x], 1);
        int p1 = atomicAdd(&cursor[d.y], 1);
        int p2 = atomicAdd(&cursor[d.z], 1);
        int p3 = atomicAdd(&cursor[d.w], 1);
        csr[p0] = s.x; csr[p1] = s.y; csr[p2] = s.z; csr[p3] = s.w;
    } else {
        for (int k = e; k < ne; k++) {
            int p = atomicAdd(&cursor[dst[k]], 1);
            csr[p] = src[k];
        }
    }
}

// ---------------- CSR mean-aggregate (half in, fp32 accum, fused epilogue) -----
template<int D4, bool FUSE, bool OUTH>
__global__ __launch_bounds__(256) void csr_agg(
    const __half* __restrict__ feat, int fstr4,
    const int* __restrict__ rowptr, const int* __restrict__ csr,
    const __half* __restrict__ r, int rstr4,
    const float* __restrict__ bias,
    void* __restrict__ outv, int ostr4, int n)
{
    const int L = (D4 < 32) ? D4 : 32;
    const int V = D4 / L;
    const int npb = 256 / L;
    int node = blockIdx.x * npb + threadIdx.x / L;
    int sl = threadIdx.x % L;
    if (node >= n) return;
    int beg = rowptr[node], end = rowptr[node + 1];
    const uint2* fH = (const uint2*)feat;
    float4 acc[V];
#pragma unroll
    for (int v = 0; v < V; v++) acc[v] = make_float4(0.f, 0.f, 0.f, 0.f);

    auto addrow = [&](int s) {
#pragma unroll
        for (int v = 0; v < V; v++) {
            uint2 u = fH[(size_t)s * fstr4 + sl + v * L];
            float2 f0 = __half22float2(*(__half2*)&u.x);
            float2 f1 = __half22float2(*(__half2*)&u.y);
            acc[v].x += f0.x; acc[v].y += f0.y;
            acc[v].z += f1.x; acc[v].w += f1.y;
        }
    };
    int j = beg;
    for (; j + 4 <= end; j += 4) {
        int s0 = __ldg(&csr[j]),     s1 = __ldg(&csr[j + 1]);
        int s2 = __ldg(&csr[j + 2]), s3 = __ldg(&csr[j + 3]);
        addrow(s0); addrow(s1); addrow(s2); addrow(s3);
    }
    for (; j < end; j++) addrow(__ldg(&csr[j]));

    float inv = 1.0f / fmaxf((float)(end - beg), 1.0f);
#pragma unroll
    for (int v = 0; v < V; v++) {
        int c4 = sl + v * L;
        float4 o = make_float4(acc[v].x * inv, acc[v].y * inv, acc[v].z * inv, acc[v].w * inv);
        if (FUSE) {
            uint2 u = ((const uint2*)r)[(size_t)node * rstr4 + c4];
            float2 r0 = __half22float2(*(__half2*)&u.x);
            float2 r1 = __half22float2(*(__half2*)&u.y);
            float4 bb = ((const float4*)bias)[c4];
            o.x += bb.x + r0.x; o.y += bb.y + r0.y;
            o.z += bb.z + r1.x; o.w += bb.w + r1.y;
            o.x = o.x > 0.f ? o.x : SLOPE * o.x;
            o.y = o.y > 0.f ? o.y : SLOPE * o.y;
            o.z = o.z > 0.f ? o.z : SLOPE * o.z;
            o.w = o.w > 0.f ? o.w : SLOPE * o.w;
        }
        if (OUTH) {
            uint2 u;
            *(__half2*)&u.x = __float22half2_rn(make_float2(o.x, o.y));
            *(__half2*)&u.y = __float22half2_rn(make_float2(o.z, o.w));
            ((uint2*)outv)[(size_t)node * ostr4 + c4] = u;
        } else {
            ((float4*)outv)[(size_t)node * ostr4 + c4] = o;
        }
    }
}

// ---------------- FP16 tensor-core GEMM (R12 config: BK=32, 3-stage) -----------
#define HSTR 40

__device__ __forceinline__ void mma_f16(float* c, const unsigned* a, const unsigned* b) {
    asm("mma.sync.aligned.m16n8k16.row.col.f32.f16.f16.f32 "
        "{%0,%1,%2,%3}, {%4,%5,%6,%7}, {%8,%9}, {%0,%1,%2,%3};"
        : "+f"(c[0]), "+f"(c[1]), "+f"(c[2]), "+f"(c[3])
        : "r"(a[0]), "r"(a[1]), "r"(a[2]), "r"(a[3]), "r"(b[0]), "r"(b[1]));
}
__device__ __forceinline__ void ldsm4(unsigned* r, unsigned addr) {
    asm volatile("ldmatrix.sync.aligned.m8n8.x4.shared.b16 {%0,%1,%2,%3}, [%4];"
                 : "=r"(r[0]), "=r"(r[1]), "=r"(r[2]), "=r"(r[3]) : "r"(addr));
}
__device__ __forceinline__ void cp16(unsigned saddr, const void* g, bool ok) {
    int sz = ok ? 16 : 0;
    asm volatile("cp.async.cg.shared.global [%0], [%1], 16, %2;"
                 :: "r"(saddr), "l"(g), "r"(sz));
}
#define CP_COMMIT() asm volatile("cp.async.commit_group;")

template<bool CONCAT, bool EPI, bool HOUT>
__global__ __launch_bounds__(256, 2) void gemm_f16(
    const __half* __restrict__ A1, const __half* __restrict__ A2, int K1,
    const __half* __restrict__ Wt, void* __restrict__ Cv,
    const float* __restrict__ bias, int M, int N, int K)
{
    constexpr int S = 3;                    // pipeline stages
    extern __shared__ __half sh[];
    __half* Asm = sh;                       // S x 128 x HSTR
    __half* Bsm = sh + S * 128 * HSTR;      // S x 128 x HSTR

    const int tid = threadIdx.x;
    const int bm = blockIdx.y * 128;
    const int bn = blockIdx.x * 128;

    const int w = tid >> 5, lane = tid & 31;
    const int wm = (w & 3) * 32;
    const int wn = (w >> 2) * 64;
    const int lr = lane >> 2, lc = lane & 3;

    const int aRow = (lane & 7) + 8 * ((lane >> 3) & 1);
    const int aK   = 8 * (lane >> 4);
    const int bRow = (lane & 7) + 8 * (lane >> 4);
    const int bK   = 8 * ((lane >> 3) & 1);

    float acc[2][8][4];
#pragma unroll
    for (int mi = 0; mi < 2; mi++)
#pragma unroll
        for (int ni = 0; ni < 8; ni++)
#pragma unroll
            for (int q = 0; q < 4; q++) acc[mi][ni][q] = 0.f;

    const int K2 = K - K1;

    auto issue = [&](int kt) {
        int stage = kt % S;
        int kg = kt * 32;
        __half* As = Asm + stage * 128 * HSTR;
        __half* Bs = Bsm + stage * 128 * HSTR;
#pragma unroll
        for (int i = 0; i < 2; i++) {
            int chunk = tid + 256 * i;
            int rr = chunk >> 2, cc = chunk & 3;
            const __half* g;
            if (CONCAT) {
                g = (kg < K1) ? A1 + (size_t)(bm + rr) * K1 + kg + cc * 8
                              : A2 + (size_t)(bm + rr) * K2 + (kg - K1) + cc * 8;
            } else {
                g = A1 + (size_t)(bm + rr) * K + kg + cc * 8;
            }
            cp16(sm32(&As[rr * HSTR + cc * 8]), g, (bm + rr) < M);
        }
#pragma unroll
        for (int i = 0; i < 2; i++) {
            int chunk = tid + 256 * i;
            int rr = chunk >> 2, cc = chunk & 3;
            const __half* g = Wt + (size_t)(bn + rr) * K + kg + cc * 8;
            cp16(sm32(&Bs[rr * HSTR + cc * 8]), g, true);
        }
        CP_COMMIT();
    };

    const int ktn = K / 32;
    issue(0);
    if (1 < ktn) issue(1);

    for (int t = 0; t < ktn; t++) {
        if (t + 1 < ktn) asm volatile("cp.async.wait_group %0;" :: "n"(1));
        else             asm volatile("cp.async.wait_group %0;" :: "n"(0));
        __syncthreads();   // tile t ready; all warps done with tile t-1's buffer
        const __half* Ab = Asm + (t % S) * 128 * HSTR;
        const __half* Bb = Bsm + (t % S) * 128 * HSTR;
#pragma unroll
        for (int kc = 0; kc < 32; kc += 16) {
            unsigned a[2][4];
#pragma unroll
            for (int mi = 0; mi < 2; mi++)
                ldsm4(a[mi], sm32(Ab + (wm + mi * 16 + aRow) * HSTR + kc + aK));
            unsigned b[8][2];
#pragma unroll
            for (int pj = 0; pj < 4; pj++) {
                unsigned r4[4];
                ldsm4(r4, sm32(Bb + (wn + pj * 16 + bRow) * HSTR + kc + bK));
                b[pj * 2][0] = r4[0]; b[pj * 2][1] = r4[1];
                b[pj * 2 + 1][0] = r4[2]; b[pj * 2 + 1][1] = r4[3];
            }
#pragma unroll
            for (int ni = 0; ni < 8; ni++) {
                mma_f16(acc[0][ni], a[0], b[ni]);
                mma_f16(acc[1][ni], a[1], b[ni]);
            }
        }
        if (t + 2 < ktn) issue(t + 2);   // overwrites buffer (t-1)%S — safe post-sync
    }

#pragma unroll
    for (int mi = 0; mi < 2; mi++) {
#pragma unroll
        for (int ni = 0; ni < 8; ni++) {
            int r0 = bm + wm + mi * 16 + lr;
            int col = bn + wn + ni * 8 + 2 * lc;
            float2 v0 = make_float2(acc[mi][ni][0], acc[mi][ni][1]);
            float2 v1 = make_float2(acc[mi][ni][2], acc[mi][ni][3]);
            if (EPI) {
                float2 bb = *(const float2*)(bias + col);
                v0.x += bb.x; v0.y += bb.y;
                v1.x += bb.x; v1.y += bb.y;
                v0.x = v0.x > 0.f ? v0.x : SLOPE * v0.x;
                v0.y = v0.y > 0.f ? v0.y : SLOPE * v0.y;
                v1.x = v1.x > 0.f ? v1.x : SLOPE * v1.x;
                v1.y = v1.y > 0.f ? v1.y : SLOPE * v1.y;
            }
            if (HOUT) {
                __half* C = (__half*)Cv;
                if (r0 < M)     *(__half2*)(C + (size_t)r0 * N + col) = __float22half2_rn(v0);
                if (r0 + 8 < M) *(__half2*)(C + (size_t)(r0 + 8) * N + col) = __float22half2_rn(v1);
            } else {
                float* C = (float*)Cv;
                if (r0 < M)     *(float2*)(C + (size_t)r0 * N + col) = v0;
                if (r0 + 8 < M) *(float2*)(C + (size_t)(r0 + 8) * N + col) = v1;
            }
        }
    }
}

// ---------------- parallel head: 4 threads per node ----------------------------
// h3h[64] -> p[32] -> leaky(q[32]) -> out[2]. 256 threads = 64 nodes/block.
__global__ __launch_bounds__(256) void head_kernel(
    const __half* __restrict__ h3,
    const float* __restrict__ Wp, const float* __restrict__ bp,
    const float* __restrict__ Wf1, const float* __restrict__ bf1,
    const float* __restrict__ Wf2, const float* __restrict__ bf2,
    float* __restrict__ out, int n)
{
    __shared__ float sWp[64 * 32], sWf1[32 * 32], sWf2[64], sbp[32], sbf1[32], sbf2[2];
    __shared__ float sP[64 * 33];   // 64 nodes x 32 (+1 pad)
    __shared__ float sQ[64 * 33];
    for (int i = threadIdx.x; i < 64 * 32; i += blockDim.x) sWp[i] = Wp[i];
    for (int i = threadIdx.x; i < 32 * 32; i += blockDim.x) sWf1[i] = Wf1[i];
    for (int i = threadIdx.x; i < 64; i += blockDim.x) sWf2[i] = Wf2[i];
    if (threadIdx.x < 32) { sbp[threadIdx.x] = bp[threadIdx.x]; sbf1[threadIdx.x] = bf1[threadIdx.x]; }
    if (threadIdx.x < 2) sbf2[threadIdx.x] = bf2[threadIdx.x];
    __syncthreads();

    const int ln  = threadIdx.x >> 2;      // local node 0..63
    const int sub = threadIdx.x & 3;       // 0..3: handles cols sub*8..sub*8+7
    const int node = blockIdx.x * 64 + ln;
    const bool ok = node < n;

    // stage 1: p[sub*8 .. sub*8+7]
    float p[8];
#pragma unroll
    for (int j = 0; j < 8; j++) p[j] = sbp[sub * 8 + j];
    if (ok) {
        const __half2* hx = (const __half2*)(h3 + (size_t)node * 64);
        for (int i2 = 0; i2 < 32; i2++) {
            float2 xf = __half22float2(hx[i2]);
#pragma unroll
            for (int j = 0; j < 8; j++) {
                p[j] = fmaf(xf.x, sWp[(2 * i2) * 32 + sub * 8 + j], p[j]);
                p[j] = fmaf(xf.y, sWp[(2 * i2 + 1) * 32 + sub * 8 + j], p[j]);
            }
        }
    }
#pragma unroll
    for (int j = 0; j < 8; j++) sP[ln * 33 + sub * 8 + j] = p[j];
    __syncthreads();

    // stage 2: q[sub*8 .. sub*8+7] = leaky(bf1 + sum_i p_i * Wf1[i][...])
    float q[8];
#pragma unroll
    for (int j = 0; j < 8; j++) q[j] = sbf1[sub * 8 + j];
    for (int i = 0; i < 32; i++) {
        float pi = sP[ln * 33 + i];
#pragma unroll
        for (int j = 0; j < 8; j++)
            q[j] = fmaf(pi, sWf1[i * 32 + sub * 8 + j], q[j]);
    }
#pragma unroll
    for (int j = 0; j < 8; j++) {
        q[j] = q[j] > 0.f ? q[j] : SLOPE * q[j];
        sQ[ln * 33 + sub * 8 + j] = q[j];
    }
    __syncthreads();

    // stage 3: subs 0,1 each compute one output
    if (ok && sub < 2) {
        float o = sbf2[sub];
        for (int i = 0; i < 32; i++)
            o = fmaf(sQ[ln * 33 + i], sWf2[i * 2 + sub], o);
        out[(size_t)node * 2 + sub] = o;
    }
}

// ---------------- launch ------------------------------------------------------
static inline int cdiv(long long a, int b) { return (int)((a + b - 1) / b); }

extern "C" void kernel_launch(void* const* d_in, const int* in_sizes, int n_in,
                              void* d_out, int out_size)
{
    const float* x   = (const float*)d_in[0];
    const int*   ei  = (const int*)d_in[1];
    // d_in[2..4] edge_attr/We/be: dead code in the reference
    const float* W1l = (const float*)d_in[5];
    const float* b1  = (const float*)d_in[6];
    const float* W1r = (const float*)d_in[7];
    const float* W2l = (const float*)d_in[8];
    const float* b2  = (const float*)d_in[9];
    const float* W2r = (const float*)d_in[10];
    const float* W3l = (const float*)d_in[11];
    const float* b3  = (const float*)d_in[12];
    const float* W3r = (const float*)d_in[13];
    const float* Wp  = (const float*)d_in[14];
    const float* bp  = (const float*)d_in[15];
    const float* Wf1 = (const float*)d_in[16];
    const float* bf1 = (const float*)d_in[17];
    const float* Wf2 = (const float*)d_in[18];
    const float* bf2 = (const float*)d_in[19];

    const int n  = in_sizes[0] / 128;   // 50000
    const int ne = in_sizes[1] / 2;     // 800000
    const int* src = ei;
    const int* dst = ei + ne;

    int *deg, *rowptr, *cursor, *csr;
    __half *xh, *wt1h, *wt2h, *wt3h, *mean1h, *h1h, *c2h, *h2h, *c3h, *h3h;
    cudaGetSymbolAddress((void**)&deg,    g_deg);
    cudaGetSymbolAddress((void**)&rowptr, g_rowptr);
    cudaGetSymbolAddress((void**)&cursor, g_cursor);
    cudaGetSymbolAddress((void**)&csr,    g_csr);
    cudaGetSymbolAddress((void**)&xh,     g_xh);
    cudaGetSymbolAddress((void**)&wt1h,   g_wt1h);
    cudaGetSymbolAddress((void**)&wt2h,   g_wt2h);
    cudaGetSymbolAddress((void**)&wt3h,   g_wt3h);
    cudaGetSymbolAddress((void**)&mean1h, g_mean1h);
    cudaGetSymbolAddress((void**)&h1h,    g_h1h);
    cudaGetSymbolAddress((void**)&c2h,    g_c2h);
    cudaGetSymbolAddress((void**)&h2h,    g_h2h);
    cudaGetSymbolAddress((void**)&c3h,    g_c3h);
    cudaGetSymbolAddress((void**)&h3h,    g_h3h);
    float* out = (float*)d_out;

    const int T = 256;
    const int gM = cdiv(n, 128);   // 391

    const int SMEM = 3 * (128 + 128) * HSTR * 2;   // 61440 B -> 2 CTAs/SM
    cudaFuncSetAttribute(gemm_f16<true, true, true>,
                         cudaFuncAttributeMaxDynamicSharedMemorySize, SMEM);
    cudaFuncSetAttribute(gemm_f16<false, false, true>,
                         cudaFuncAttributeMaxDynamicSharedMemorySize, SMEM);

    // ---- fused prologue: deg count (4 edges/thread) + x->half + weight prep
    cudaMemsetAsync(deg, 0, (size_t)n * sizeof(int));
    const int CB = cdiv(cdiv(ne, 4), T);
    const int XB = cdiv((long long)n * 32, T);
    const int PB = cdiv(512 * 256 + 512 * 512 + 128 * 256, T);
    prologue_kernel<<<CB + XB + PB, T>>>(dst, deg, ne, x, n * 32,
                                         W1l, W1r, W2l, W2r, W3l, W3r, CB, XB);
    scan_kernel<<<1, 1024>>>(deg, rowptr, cursor, n);
    scatter_kernel<<<cdiv(cdiv(ne, 4), T), T>>>(src, dst, cursor, csr, ne);

    // ---- layer 1: mean1h = mean_csr(xh); h1h = leaky([mean1h|xh] @ wt1h^T + b1)
    csr_agg<32, false, true><<<cdiv(n, 8), T>>>(xh, 32, rowptr, csr,
                                                nullptr, 0, nullptr, mean1h, 32, n);
    gemm_f16<true, true, true><<<dim3(4, gM), 256, SMEM>>>(
        mean1h, xh, 128, wt1h, h1h, b1, n, 512, 256);

    // ---- layer 2: c2h = [z2|r2] = h1h @ wt2h^T; h2h = leaky(mean+b2+r2)
    gemm_f16<false, false, true><<<dim3(4, gM), 256, SMEM>>>(
        h1h, nullptr, 0, wt2h, c2h, nullptr, n, 512, 512);
    csr_agg<64, true, true><<<cdiv(n, 8), T>>>(c2h, 128, rowptr, csr,
                                               c2h + 256, 128, b2, h2h, 64, n);

    // ---- layer 3: c3h = [z3|r3] = h2h @ wt3h^T; h3h = leaky(mean+b3+r3)
    gemm_f16<false, false, true><<<dim3(1, gM), 256, SMEM>>>(
        h2h, nullptr, 0, wt3h, c3h, nullptr, n, 128, 256);
    csr_agg<16, true, true><<<cdiv(n, 16), T>>>(c3h, 32, rowptr, csr,
                                                c3h + 64, 32, b3, h3h, 16, n);

    // ---- parallel head
    head_kernel<<<cdiv(n, 64), 256>>>(h3h, Wp, bp, Wf1, bf1, Wf2, bf2, out, n);
}

// round 15
// speedup vs baseline: 1.2567x; 1.2567x over previous
#include <cuda_runtime.h>
#include <cuda_fp16.h>
#include <cstdint>

#define SLOPE 0.15f

static const int NN = 50000;
static const int NE = 800000;

// ---------------- device scratch ----------------------------------------------
__device__ int    g_deg[NN];
__device__ int    g_part[256];
__device__ int    g_rowptr[NN + 1];
__device__ int    g_cursor[NN];
__device__ int    g_csr[NE];
__device__ __half g_xh[(size_t)NN * 128];
__device__ __half g_wt1h[512 * 256];
__device__ __half g_wt2h[512 * 512];
__device__ __half g_wt3h[128 * 256];
__device__ __half g_mean1h[(size_t)NN * 128];
__device__ __half g_h1h[(size_t)NN * 512];
__device__ __half g_c2h[(size_t)NN * 512];    // [z2 | r2]
__device__ __half g_h2h[NN * 256];
__device__ __half g_c3h[NN * 128];            // [z3 | r3]
__device__ __half g_h3h[NN * 64];

__device__ __forceinline__ unsigned sm32(const void* p) {
    return (unsigned)__cvta_generic_to_shared(p);
}

// ---------------- fused prologue: deg count + x->half + weight prep ------------
__global__ void prologue_kernel(
    const int* __restrict__ dst, int* __restrict__ deg, int ne,
    const float* __restrict__ x, int n4x,
    const float* __restrict__ W1l, const float* __restrict__ W1r,
    const float* __restrict__ W2l, const float* __restrict__ W2r,
    const float* __restrict__ W3l, const float* __restrict__ W3r,
    int CB, int XB)
{
    int b = blockIdx.x;
    if (b < CB) {
        int e = (b * 256 + threadIdx.x) * 4;
        if (e + 3 < ne) {
            int4 d = *(const int4*)(dst + e);
            atomicAdd(&deg[d.x], 1);
            atomicAdd(&deg[d.y], 1);
            atomicAdd(&deg[d.z], 1);
            atomicAdd(&deg[d.w], 1);
        } else {
            for (int k = e; k < ne; k++) atomicAdd(&deg[dst[k]], 1);
        }
        return;
    }
    b -= CB;
    if (b < XB) {
        int i = b * 256 + threadIdx.x;
        if (i >= n4x) return;
        float4 v = ((const float4*)x)[i];
        __half2* o = (__half2*)g_xh + (size_t)i * 2;
        o[0] = __float22half2_rn(make_float2(v.x, v.y));
        o[1] = __float22half2_rn(make_float2(v.z, v.w));
        return;
    }
    b -= XB;
    int i = b * 256 + threadIdx.x;
    if (i < 512 * 256) {
        int nn = i >> 8, k = i & 255;
        float v = (k < 128) ? W1l[k * 512 + nn] : W1r[(k - 128) * 512 + nn];
        g_wt1h[i] = __float2half_rn(v);
        return;
    }
    int j = i - 512 * 256;
    if (j < 512 * 512) {
        int nn = j >> 9, k = j & 511;
        float v = (nn < 256) ? W2l[k * 256 + nn] : W2r[k * 256 + (nn - 256)];
        g_wt2h[j] = __float2half_rn(v);
        return;
    }
    int l = j - 512 * 512;
    if (l < 128 * 256) {
        int nn = l >> 8, k = l & 255;
        float v = (nn < 64) ? W3l[k * 64 + nn] : W3r[k * 64 + (nn - 64)];
        g_wt3h[l] = __float2half_rn(v);
    }
}

// ---------------- 3-phase coalesced CSR scan ------------------------------------
__global__ void scanA(const int* __restrict__ deg, int* __restrict__ part, int n) {
    __shared__ int s[256];
    int i = blockIdx.x * 256 + threadIdx.x;
    s[threadIdx.x] = (i < n) ? deg[i] : 0;
    __syncthreads();
    for (int off = 128; off > 0; off >>= 1) {
        if (threadIdx.x < off) s[threadIdx.x] += s[threadIdx.x + off];
        __syncthreads();
    }
    if (threadIdx.x == 0) part[blockIdx.x] = s[0];
}

__global__ void scanB(int* __restrict__ part, int* __restrict__ rowptr_n, int nb) {
    __shared__ int s[256];
    int v = (threadIdx.x < nb) ? part[threadIdx.x] : 0;
    s[threadIdx.x] = v;
    __syncthreads();
    for (int off = 1; off < 256; off <<= 1) {
        int t = (threadIdx.x >= off) ? s[threadIdx.x - off] : 0;
        __syncthreads();
        s[threadIdx.x] += t;
        __syncthreads();
    }
    if (threadIdx.x < nb) part[threadIdx.x] = s[threadIdx.x] - v;  // exclusive
    if (threadIdx.x == nb - 1) rowptr_n[0] = s[threadIdx.x];       // total
}

__global__ void scanC(const int* __restrict__ deg, const int* __restrict__ part,
                      int* __restrict__ rowptr, int* __restrict__ cursor, int n) {
    __shared__ int s[256];
    int i = blockIdx.x * 256 + threadIdx.x;
    int d = (i < n) ? deg[i] : 0;
    s[threadIdx.x] = d;
    __syncthreads();
    for (int off = 1; off < 256; off <<= 1) {
        int t = (threadIdx.x >= off) ? s[threadIdx.x - off] : 0;
        __syncthreads();
        s[threadIdx.x] += t;
        __syncthreads();
    }
    if (i < n) {
        int r = part[blockIdx.x] + s[threadIdx.x] - d;  // exclusive prefix
        rowptr[i] = r;
        cursor[i] = r;
    }
}

__global__ void scatter_kernel(const int* __restrict__ src, const int* __restrict__ dst,
                               int* __restrict__ cursor, int* __restrict__ csr, int ne) {
    int e = (blockIdx.x * blockDim.x + threadIdx.x) * 4;
    if (e + 3 < ne) {
        int4 s = *(const int4*)(src + e);
        int4 d = *(const int4*)(dst + e);
        int p0 = atomicAdd(&cursor[d.x], 1);
        int p1 = atomicAdd(&cursor[d.y], 1);
        int p2 = atomicAdd(&cursor[d.z], 1);
        int p3 = atomicAdd(&cursor[d.w], 1);
        csr[p0] = s.x; csr[p1] = s.y; csr[p2] = s.z; csr[p3] = s.w;
    } else {
        for (int k = e; k < ne; k++) {
            int p = atomicAdd(&cursor[dst[k]], 1);
            csr[p] = src[k];
        }
    }
}

// ---------------- CSR mean-aggregate (half in, fp32 accum, fused epilogue) -----
template<int D4, bool FUSE, bool OUTH>
__global__ __launch_bounds__(256) void csr_agg(
    const __half* __restrict__ feat, int fstr4,
    const int* __restrict__ rowptr, const int* __restrict__ csr,
    const __half* __restrict__ r, int rstr4,
    const float* __restrict__ bias,
    void* __restrict__ outv, int ostr4, int n)
{
    const int L = (D4 < 32) ? D4 : 32;
    const int V = D4 / L;
    const int npb = 256 / L;
    int node = blockIdx.x * npb + threadIdx.x / L;
    int sl = threadIdx.x % L;
    if (node >= n) return;
    int beg = rowptr[node], end = rowptr[node + 1];
    const uint2* fH = (const uint2*)feat;
    float4 acc[V];
#pragma unroll
    for (int v = 0; v < V; v++) acc[v] = make_float4(0.f, 0.f, 0.f, 0.f);

    auto addrow = [&](int s) {
#pragma unroll
        for (int v = 0; v < V; v++) {
            uint2 u = fH[(size_t)s * fstr4 + sl + v * L];
            float2 f0 = __half22float2(*(__half2*)&u.x);
            float2 f1 = __half22float2(*(__half2*)&u.y);
            acc[v].x += f0.x; acc[v].y += f0.y;
            acc[v].z += f1.x; acc[v].w += f1.y;
        }
    };
    int j = beg;
    for (; j + 4 <= end; j += 4) {
        int s0 = __ldg(&csr[j]),     s1 = __ldg(&csr[j + 1]);
        int s2 = __ldg(&csr[j + 2]), s3 = __ldg(&csr[j + 3]);
        addrow(s0); addrow(s1); addrow(s2); addrow(s3);
    }
    for (; j < end; j++) addrow(__ldg(&csr[j]));

    float inv = 1.0f / fmaxf((float)(end - beg), 1.0f);
#pragma unroll
    for (int v = 0; v < V; v++) {
        int c4 = sl + v * L;
        float4 o = make_float4(acc[v].x * inv, acc[v].y * inv, acc[v].z * inv, acc[v].w * inv);
        if (FUSE) {
            uint2 u = ((const uint2*)r)[(size_t)node * rstr4 + c4];
            float2 r0 = __half22float2(*(__half2*)&u.x);
            float2 r1 = __half22float2(*(__half2*)&u.y);
            float4 bb = ((const float4*)bias)[c4];
            o.x += bb.x + r0.x; o.y += bb.y + r0.y;
            o.z += bb.z + r1.x; o.w += bb.w + r1.y;
            o.x = o.x > 0.f ? o.x : SLOPE * o.x;
            o.y = o.y > 0.f ? o.y : SLOPE * o.y;
            o.z = o.z > 0.f ? o.z : SLOPE * o.z;
            o.w = o.w > 0.f ? o.w : SLOPE * o.w;
        }
        if (OUTH) {
            uint2 u;
            *(__half2*)&u.x = __float22half2_rn(make_float2(o.x, o.y));
            *(__half2*)&u.y = __float22half2_rn(make_float2(o.z, o.w));
            ((uint2*)outv)[(size_t)node * ostr4 + c4] = u;
        } else {
            ((float4*)outv)[(size_t)node * ostr4 + c4] = o;
        }
    }
}

// ---------------- FP16 tensor-core GEMM (R12 config: BK=32, 3-stage) -----------
#define HSTR 40

__device__ __forceinline__ void mma_f16(float* c, const unsigned* a, const unsigned* b) {
    asm("mma.sync.aligned.m16n8k16.row.col.f32.f16.f16.f32 "
        "{%0,%1,%2,%3}, {%4,%5,%6,%7}, {%8,%9}, {%0,%1,%2,%3};"
        : "+f"(c[0]), "+f"(c[1]), "+f"(c[2]), "+f"(c[3])
        : "r"(a[0]), "r"(a[1]), "r"(a[2]), "r"(a[3]), "r"(b[0]), "r"(b[1]));
}
__device__ __forceinline__ void ldsm4(unsigned* r, unsigned addr) {
    asm volatile("ldmatrix.sync.aligned.m8n8.x4.shared.b16 {%0,%1,%2,%3}, [%4];"
                 : "=r"(r[0]), "=r"(r[1]), "=r"(r[2]), "=r"(r[3]) : "r"(addr));
}
__device__ __forceinline__ void cp16(unsigned saddr, const void* g, bool ok) {
    int sz = ok ? 16 : 0;
    asm volatile("cp.async.cg.shared.global [%0], [%1], 16, %2;"
                 :: "r"(saddr), "l"(g), "r"(sz));
}
#define CP_COMMIT() asm volatile("cp.async.commit_group;")

template<bool CONCAT, bool EPI, bool HOUT>
__global__ __launch_bounds__(256, 2) void gemm_f16(
    const __half* __restrict__ A1, const __half* __restrict__ A2, int K1,
    const __half* __restrict__ Wt, void* __restrict__ Cv,
    const float* __restrict__ bias, int M, int N, int K)
{
    constexpr int S = 3;                    // pipeline stages
    extern __shared__ __half sh[];
    __half* Asm = sh;                       // S x 128 x HSTR
    __half* Bsm = sh + S * 128 * HSTR;      // S x 128 x HSTR

    const int tid = threadIdx.x;
    const int bm = blockIdx.y * 128;
    const int bn = blockIdx.x * 128;

    const int w = tid >> 5, lane = tid & 31;
    const int wm = (w & 3) * 32;
    const int wn = (w >> 2) * 64;
    const int lr = lane >> 2, lc = lane & 3;

    const int aRow = (lane & 7) + 8 * ((lane >> 3) & 1);
    const int aK   = 8 * (lane >> 4);
    const int bRow = (lane & 7) + 8 * (lane >> 4);
    const int bK   = 8 * ((lane >> 3) & 1);

    float acc[2][8][4];
#pragma unroll
    for (int mi = 0; mi < 2; mi++)
#pragma unroll
        for (int ni = 0; ni < 8; ni++)
#pragma unroll
            for (int q = 0; q < 4; q++) acc[mi][ni][q] = 0.f;

    const int K2 = K - K1;

    auto issue = [&](int kt) {
        int stage = kt % S;
        int kg = kt * 32;
        __half* As = Asm + stage * 128 * HSTR;
        __half* Bs = Bsm + stage * 128 * HSTR;
#pragma unroll
        for (int i = 0; i < 2; i++) {
            int chunk = tid + 256 * i;
            int rr = chunk >> 2, cc = chunk & 3;
            const __half* g;
            if (CONCAT) {
                g = (kg < K1) ? A1 + (size_t)(bm + rr) * K1 + kg + cc * 8
                              : A2 + (size_t)(bm + rr) * K2 + (kg - K1) + cc * 8;
            } else {
                g = A1 + (size_t)(bm + rr) * K + kg + cc * 8;
            }
            cp16(sm32(&As[rr * HSTR + cc * 8]), g, (bm + rr) < M);
        }
#pragma unroll
        for (int i = 0; i < 2; i++) {
            int chunk = tid + 256 * i;
            int rr = chunk >> 2, cc = chunk & 3;
            const __half* g = Wt + (size_t)(bn + rr) * K + kg + cc * 8;
            cp16(sm32(&Bs[rr * HSTR + cc * 8]), g, true);
        }
        CP_COMMIT();
    };

    const int ktn = K / 32;
    issue(0);
    if (1 < ktn) issue(1);

    for (int t = 0; t < ktn; t++) {
        if (t + 1 < ktn) asm volatile("cp.async.wait_group %0;" :: "n"(1));
        else             asm volatile("cp.async.wait_group %0;" :: "n"(0));
        __syncthreads();   // tile t ready; all warps done with tile t-1's buffer
        const __half* Ab = Asm + (t % S) * 128 * HSTR;
        const __half* Bb = Bsm + (t % S) * 128 * HSTR;
#pragma unroll
        for (int kc = 0; kc < 32; kc += 16) {
            unsigned a[2][4];
#pragma unroll
            for (int mi = 0; mi < 2; mi++)
                ldsm4(a[mi], sm32(Ab + (wm + mi * 16 + aRow) * HSTR + kc + aK));
            unsigned b[8][2];
#pragma unroll
            for (int pj = 0; pj < 4; pj++) {
                unsigned r4[4];
                ldsm4(r4, sm32(Bb + (wn + pj * 16 + bRow) * HSTR + kc + bK));
                b[pj * 2][0] = r4[0]; b[pj * 2][1] = r4[1];
                b[pj * 2 + 1][0] = r4[2]; b[pj * 2 + 1][1] = r4[3];
            }
#pragma unroll
            for (int ni = 0; ni < 8; ni++) {
                mma_f16(acc[0][ni], a[0], b[ni]);
                mma_f16(acc[1][ni], a[1], b[ni]);
            }
        }
        if (t + 2 < ktn) issue(t + 2);   // overwrites buffer (t-1)%S — safe post-sync
    }

#pragma unroll
    for (int mi = 0; mi < 2; mi++) {
#pragma unroll
        for (int ni = 0; ni < 8; ni++) {
            int r0 = bm + wm + mi * 16 + lr;
            int col = bn + wn + ni * 8 + 2 * lc;
            float2 v0 = make_float2(acc[mi][ni][0], acc[mi][ni][1]);
            float2 v1 = make_float2(acc[mi][ni][2], acc[mi][ni][3]);
            if (EPI) {
                float2 bb = *(const float2*)(bias + col);
                v0.x += bb.x; v0.y += bb.y;
                v1.x += bb.x; v1.y += bb.y;
                v0.x = v0.x > 0.f ? v0.x : SLOPE * v0.x;
                v0.y = v0.y > 0.f ? v0.y : SLOPE * v0.y;
                v1.x = v1.x > 0.f ? v1.x : SLOPE * v1.x;
                v1.y = v1.y > 0.f ? v1.y : SLOPE * v1.y;
            }
            if (HOUT) {
                __half* C = (__half*)Cv;
                if (r0 < M)     *(__half2*)(C + (size_t)r0 * N + col) = __float22half2_rn(v0);
                if (r0 + 8 < M) *(__half2*)(C + (size_t)(r0 + 8) * N + col) = __float22half2_rn(v1);
            } else {
                float* C = (float*)Cv;
                if (r0 < M)     *(float2*)(C + (size_t)r0 * N + col) = v0;
                if (r0 + 8 < M) *(float2*)(C + (size_t)(r0 + 8) * N + col) = v1;
            }
        }
    }
}

// ---------------- fused head (R12 serial version) ------------------------------
__global__ __launch_bounds__(128) void head_kernel(
    const __half* __restrict__ h3,
    const float* __restrict__ Wp, const float* __restrict__ bp,
    const float* __restrict__ Wf1, const float* __restrict__ bf1,
    const float* __restrict__ Wf2, const float* __restrict__ bf2,
    float* __restrict__ out, int n)
{
    __shared__ float sWp[64 * 32], sWf1[32 * 32], sWf2[64], sbp[32], sbf1[32], sbf2[2];
    for (int i = threadIdx.x; i < 64 * 32; i += blockDim.x) sWp[i] = Wp[i];
    for (int i = threadIdx.x; i < 32 * 32; i += blockDim.x) sWf1[i] = Wf1[i];
    for (int i = threadIdx.x; i < 64; i += blockDim.x) sWf2[i] = Wf2[i];
    if (threadIdx.x < 32) { sbp[threadIdx.x] = bp[threadIdx.x]; sbf1[threadIdx.x] = bf1[threadIdx.x]; }
    if (threadIdx.x < 2) sbf2[threadIdx.x] = bf2[threadIdx.x];
    __syncthreads();
    int nidx = blockIdx.x * blockDim.x + threadIdx.x;
    if (nidx >= n) return;

    float p[32];
#pragma unroll
    for (int j = 0; j < 32; j++) p[j] = sbp[j];
    const __half2* hx = (const __half2*)(h3 + (size_t)nidx * 64);
    for (int i2 = 0; i2 < 32; i2++) {
        float2 xf = __half22float2(hx[i2]);
#pragma unroll
        for (int j = 0; j < 32; j++) {
            p[j] = fmaf(xf.x, sWp[(2 * i2) * 32 + j], p[j]);
            p[j] = fmaf(xf.y, sWp[(2 * i2 + 1) * 32 + j], p[j]);
        }
    }
    float q[32];
#pragma unroll
    for (int j = 0; j < 32; j++) q[j] = sbf1[j];
#pragma unroll
    for (int i = 0; i < 32; i++) {
#pragma unroll
        for (int j = 0; j < 32; j++) q[j] = fmaf(p[i], sWf1[i * 32 + j], q[j]);
    }
#pragma unroll
    for (int j = 0; j < 32; j++) q[j] = q[j] > 0.f ? q[j] : SLOPE * q[j];
    float o0 = sbf2[0], o1 = sbf2[1];
#pragma unroll
    for (int i = 0; i < 32; i++) { o0 = fmaf(q[i], sWf2[i * 2], o0); o1 = fmaf(q[i], sWf2[i * 2 + 1], o1); }
    out[(size_t)nidx * 2]     = o0;
    out[(size_t)nidx * 2 + 1] = o1;
}

// ---------------- launch ------------------------------------------------------
static inline int cdiv(long long a, int b) { return (int)((a + b - 1) / b); }

extern "C" void kernel_launch(void* const* d_in, const int* in_sizes, int n_in,
                              void* d_out, int out_size)
{
    const float* x   = (const float*)d_in[0];
    const int*   ei  = (const int*)d_in[1];
    // d_in[2..4] edge_attr/We/be: dead code in the reference
    const float* W1l = (const float*)d_in[5];
    const float* b1  = (const float*)d_in[6];
    const float* W1r = (const float*)d_in[7];
    const float* W2l = (const float*)d_in[8];
    const float* b2  = (const float*)d_in[9];
    const float* W2r = (const float*)d_in[10];
    const float* W3l = (const float*)d_in[11];
    const float* b3  = (const float*)d_in[12];
    const float* W3r = (const float*)d_in[13];
    const float* Wp  = (const float*)d_in[14];
    const float* bp  = (const float*)d_in[15];
    const float* Wf1 = (const float*)d_in[16];
    const float* bf1 = (const float*)d_in[17];
    const float* Wf2 = (const float*)d_in[18];
    const float* bf2 = (const float*)d_in[19];

    const int n  = in_sizes[0] / 128;   // 50000
    const int ne = in_sizes[1] / 2;     // 800000
    const int* src = ei;
    const int* dst = ei + ne;

    int *deg, *part, *rowptr, *cursor, *csr;
    __half *xh, *wt1h, *wt2h, *wt3h, *mean1h, *h1h, *c2h, *h2h, *c3h, *h3h;
    cudaGetSymbolAddress((void**)&deg,    g_deg);
    cudaGetSymbolAddress((void**)&part,   g_part);
    cudaGetSymbolAddress((void**)&rowptr, g_rowptr);
    cudaGetSymbolAddress((void**)&cursor, g_cursor);
    cudaGetSymbolAddress((void**)&csr,    g_csr);
    cudaGetSymbolAddress((void**)&xh,     g_xh);
    cudaGetSymbolAddress((void**)&wt1h,   g_wt1h);
    cudaGetSymbolAddress((void**)&wt2h,   g_wt2h);
    cudaGetSymbolAddress((void**)&wt3h,   g_wt3h);
    cudaGetSymbolAddress((void**)&mean1h, g_mean1h);
    cudaGetSymbolAddress((void**)&h1h,    g_h1h);
    cudaGetSymbolAddress((void**)&c2h,    g_c2h);
    cudaGetSymbolAddress((void**)&h2h,    g_h2h);
    cudaGetSymbolAddress((void**)&c3h,    g_c3h);
    cudaGetSymbolAddress((void**)&h3h,    g_h3h);
    float* out = (float*)d_out;

    const int T = 256;
    const int gM = cdiv(n, 128);   // 391
    const int NB = cdiv(n, 256);   // 196 scan blocks

    const int SMEM = 3 * (128 + 128) * HSTR * 2;   // 61440 B -> 2 CTAs/SM
    cudaFuncSetAttribute(gemm_f16<true, true, true>,
                         cudaFuncAttributeMaxDynamicSharedMemorySize, SMEM);
    cudaFuncSetAttribute(gemm_f16<false, false, true>,
                         cudaFuncAttributeMaxDynamicSharedMemorySize, SMEM);

    // ---- fused prologue: deg count (4 edges/thread) + x->half + weight prep
    cudaMemsetAsync(deg, 0, (size_t)n * sizeof(int));
    const int CB = cdiv(cdiv(ne, 4), T);
    const int XB = cdiv((long long)n * 32, T);
    const int PB = cdiv(512 * 256 + 512 * 512 + 128 * 256, T);
    prologue_kernel<<<CB + XB + PB, T>>>(dst, deg, ne, x, n * 32,
                                         W1l, W1r, W2l, W2r, W3l, W3r, CB, XB);

    // ---- 3-phase coalesced scan -> rowptr/cursor
    scanA<<<NB, 256>>>(deg, part, n);
    scanB<<<1, 256>>>(part, rowptr + n, NB);
    scanC<<<NB, 256>>>(deg, part, rowptr, cursor, n);
    scatter_kernel<<<cdiv(cdiv(ne, 4), T), T>>>(src, dst, cursor, csr, ne);

    // ---- layer 1: mean1h = mean_csr(xh); h1h = leaky([mean1h|xh] @ wt1h^T + b1)
    csr_agg<32, false, true><<<cdiv(n, 8), T>>>(xh, 32, rowptr, csr,
                                                nullptr, 0, nullptr, mean1h, 32, n);
    gemm_f16<true, true, true><<<dim3(4, gM), 256, SMEM>>>(
        mean1h, xh, 128, wt1h, h1h, b1, n, 512, 256);

    // ---- layer 2: c2h = [z2|r2] = h1h @ wt2h^T; h2h = leaky(mean+b2+r2)
    gemm_f16<false, false, true><<<dim3(4, gM), 256, SMEM>>>(
        h1h, nullptr, 0, wt2h, c2h, nullptr, n, 512, 512);
    csr_agg<64, true, true><<<cdiv(n, 8), T>>>(c2h, 128, rowptr, csr,
                                               c2h + 256, 128, b2, h2h, 64, n);

    // ---- layer 3: c3h = [z3|r3] = h2h @ wt3h^T; h3h = leaky(mean+b3+r3)
    gemm_f16<false, false, true><<<dim3(1, gM), 256, SMEM>>>(
        h2h, nullptr, 0, wt3h, c3h, nullptr, n, 128, 256);
    csr_agg<16, true, true><<<cdiv(n, 16), T>>>(c3h, 32, rowptr, csr,
                                                c3h + 64, 32, b3, h3h, 16, n);

    // ---- fused head (serial per-node, R12 version)
    head_kernel<<<cdiv(n, 128), 128>>>(h3h, Wp, bp, Wf1, bf1, Wf2, bf2, out, n);
}

// round 16
// speedup vs baseline: 1.2702x; 1.0107x over previous
#include <cuda_runtime.h>
#include <cuda_fp16.h>
#include <cstdint>

#define SLOPE 0.15f

static const int NN = 50000;
static const int NE = 800000;

// ---------------- device scratch ----------------------------------------------
__device__ int    g_deg[NN];
__device__ int    g_part[256];
__device__ int    g_rowptr[NN + 1];
__device__ int    g_cursor[NN];
__device__ int    g_csr[NE];
__device__ __half g_xh[(size_t)NN * 128];
__device__ __half g_wt1h[512 * 256];
__device__ __half g_wt2h[512 * 512];
__device__ __half g_wt3h[128 * 256];
__device__ __half g_mean1h[(size_t)NN * 128];
__device__ __half g_h1h[(size_t)NN * 512];
__device__ __half g_c2h[(size_t)NN * 512];    // [z2 | r2]
__device__ __half g_h2h[NN * 256];
__device__ __half g_c3h[NN * 128];            // [z3 | r3]
__device__ __half g_h3h[NN * 64];

__device__ __forceinline__ unsigned sm32(const void* p) {
    return (unsigned)__cvta_generic_to_shared(p);
}
// PDL primitives: no-ops when launched without the PDL attribute.
__device__ __forceinline__ void gdl() {
    asm volatile("griddepcontrol.launch_dependents;");
}
__device__ __forceinline__ void gds() {
    asm volatile("griddepcontrol.wait;" ::: "memory");
}

// ---------------- fused prologue: deg count + x->half + weight prep ------------
__global__ void prologue_kernel(
    const int* __restrict__ dst, int* __restrict__ deg, int ne,
    const float* __restrict__ x, int n4x,
    const float* __restrict__ W1l, const float* __restrict__ W1r,
    const float* __restrict__ W2l, const float* __restrict__ W2r,
    const float* __restrict__ W3l, const float* __restrict__ W3r,
    int CB, int XB)
{
    gdl();
    int b = blockIdx.x;
    if (b < CB) {
        int e = (b * 256 + threadIdx.x) * 4;
        if (e + 3 < ne) {
            int4 d = *(const int4*)(dst + e);
            atomicAdd(&deg[d.x], 1);
            atomicAdd(&deg[d.y], 1);
            atomicAdd(&deg[d.z], 1);
            atomicAdd(&deg[d.w], 1);
        } else {
            for (int k = e; k < ne; k++) atomicAdd(&deg[dst[k]], 1);
        }
        return;
    }
    b -= CB;
    if (b < XB) {
        int i = b * 256 + threadIdx.x;
        if (i >= n4x) return;
        float4 v = ((const float4*)x)[i];
        __half2* o = (__half2*)g_xh + (size_t)i * 2;
        o[0] = __float22half2_rn(make_float2(v.x, v.y));
        o[1] = __float22half2_rn(make_float2(v.z, v.w));
        return;
    }
    b -= XB;
    int i = b * 256 + threadIdx.x;
    if (i < 512 * 256) {
        int nn = i >> 8, k = i & 255;
        float v = (k < 128) ? W1l[k * 512 + nn] : W1r[(k - 128) * 512 + nn];
        g_wt1h[i] = __float2half_rn(v);
        return;
    }
    int j = i - 512 * 256;
    if (j < 512 * 512) {
        int nn = j >> 9, k = j & 511;
        float v = (nn < 256) ? W2l[k * 256 + nn] : W2r[k * 256 + (nn - 256)];
        g_wt2h[j] = __float2half_rn(v);
        return;
    }
    int l = j - 512 * 512;
    if (l < 128 * 256) {
        int nn = l >> 8, k = l & 255;
        float v = (nn < 64) ? W3l[k * 64 + nn] : W3r[k * 64 + (nn - 64)];
        g_wt3h[l] = __float2half_rn(v);
    }
}

// ---------------- coalesced CSR scan (2 kernels) --------------------------------
__global__ void scanA(const int* __restrict__ deg, int* __restrict__ part, int n) {
    gdl();
    __shared__ int s[256];
    gds();
    int i = blockIdx.x * 256 + threadIdx.x;
    s[threadIdx.x] = (i < n) ? deg[i] : 0;
    __syncthreads();
    for (int off = 128; off > 0; off >>= 1) {
        if (threadIdx.x < off) s[threadIdx.x] += s[threadIdx.x + off];
        __syncthreads();
    }
    if (threadIdx.x == 0) part[blockIdx.x] = s[0];
}

// scanC: per-block redundant scan of partials (replaces separate scanB)
__global__ void scanC(const int* __restrict__ deg, const int* __restrict__ part,
                      int* __restrict__ rowptr, int* __restrict__ cursor,
                      int n, int nb, int ne) {
    gdl();
    __shared__ int sp[256];
    __shared__ int s[256];
    gds();
    const int t = threadIdx.x;
    sp[t] = (t < nb) ? part[t] : 0;
    __syncthreads();
    for (int off = 1; off < 256; off <<= 1) {
        int v = (t >= off) ? sp[t - off] : 0;
        __syncthreads();
        sp[t] += v;
        __syncthreads();
    }
    int base = (blockIdx.x == 0) ? 0 : sp[blockIdx.x - 1];
    int i = blockIdx.x * 256 + t;
    int d = (i < n) ? deg[i] : 0;
    s[t] = d;
    __syncthreads();
    for (int off = 1; off < 256; off <<= 1) {
        int v = (t >= off) ? s[t - off] : 0;
        __syncthreads();
        s[t] += v;
        __syncthreads();
    }
    if (i < n) {
        int r = base + s[t] - d;   // exclusive prefix
        rowptr[i] = r;
        cursor[i] = r;
    }
    if (blockIdx.x == 0 && t == 0) rowptr[n] = ne;  // total = edge count
}

__global__ void scatter_kernel(const int* __restrict__ src, const int* __restrict__ dst,
                               int* __restrict__ cursor, int* __restrict__ csr, int ne) {
    gdl();
    gds();
    int e = (blockIdx.x * blockDim.x + threadIdx.x) * 4;
    if (e + 3 < ne) {
        int4 s = *(const int4*)(src + e);
        int4 d = *(const int4*)(dst + e);
        int p0 = atomicAdd(&cursor[d.x], 1);
        int p1 = atomicAdd(&cursor[d.y], 1);
        int p2 = atomicAdd(&cursor[d.z], 1);
        int p3 = atomicAdd(&cursor[d.w], 1);
        csr[p0] = s.x; csr[p1] = s.y; csr[p2] = s.z; csr[p3] = s.w;
    } else {
        for (int k = e; k < ne; k++) {
            int p = atomicAdd(&cursor[dst[k]], 1);
            csr[p] = src[k];
        }
    }
}

// ---------------- CSR mean-aggregate (half in, fp32 accum, fused epilogue) -----
template<int D4, bool FUSE, bool OUTH>
__global__ __launch_bounds__(256) void csr_agg(
    const __half* __restrict__ feat, int fstr4,
    const int* __restrict__ rowptr, const int* __restrict__ csr,
    const __half* __restrict__ r, int rstr4,
    const float* __restrict__ bias,
    void* __restrict__ outv, int ostr4, int n)
{
    gdl();
    const int L = (D4 < 32) ? D4 : 32;
    const int V = D4 / L;
    const int npb = 256 / L;
    int node = blockIdx.x * npb + threadIdx.x / L;
    int sl = threadIdx.x % L;
    gds();
    if (node >= n) return;
    int beg = rowptr[node], end = rowptr[node + 1];
    const uint2* fH = (const uint2*)feat;
    float4 acc[V];
#pragma unroll
    for (int v = 0; v < V; v++) acc[v] = make_float4(0.f, 0.f, 0.f, 0.f);

    auto addrow = [&](int s) {
#pragma unroll
        for (int v = 0; v < V; v++) {
            uint2 u = fH[(size_t)s * fstr4 + sl + v * L];
            float2 f0 = __half22float2(*(__half2*)&u.x);
            float2 f1 = __half22float2(*(__half2*)&u.y);
            acc[v].x += f0.x; acc[v].y += f0.y;
            acc[v].z += f1.x; acc[v].w += f1.y;
        }
    };
    int j = beg;
    for (; j + 4 <= end; j += 4) {
        int s0 = __ldg(&csr[j]),     s1 = __ldg(&csr[j + 1]);
        int s2 = __ldg(&csr[j + 2]), s3 = __ldg(&csr[j + 3]);
        addrow(s0); addrow(s1); addrow(s2); addrow(s3);
    }
    for (; j < end; j++) addrow(__ldg(&csr[j]));

    float inv = 1.0f / fmaxf((float)(end - beg), 1.0f);
#pragma unroll
    for (int v = 0; v < V; v++) {
        int c4 = sl + v * L;
        float4 o = make_float4(acc[v].x * inv, acc[v].y * inv, acc[v].z * inv, acc[v].w * inv);
        if (FUSE) {
            uint2 u = ((const uint2*)r)[(size_t)node * rstr4 + c4];
            float2 r0 = __half22float2(*(__half2*)&u.x);
            float2 r1 = __half22float2(*(__half2*)&u.y);
            float4 bb = ((const float4*)bias)[c4];
            o.x += bb.x + r0.x; o.y += bb.y + r0.y;
            o.z += bb.z + r1.x; o.w += bb.w + r1.y;
            o.x = o.x > 0.f ? o.x : SLOPE * o.x;
            o.y = o.y > 0.f ? o.y : SLOPE * o.y;
            o.z = o.z > 0.f ? o.z : SLOPE * o.z;
            o.w = o.w > 0.f ? o.w : SLOPE * o.w;
        }
        if (OUTH) {
            uint2 u;
            *(__half2*)&u.x = __float22half2_rn(make_float2(o.x, o.y));
            *(__half2*)&u.y = __float22half2_rn(make_float2(o.z, o.w));
            ((uint2*)outv)[(size_t)node * ostr4 + c4] = u;
        } else {
            ((float4*)outv)[(size_t)node * ostr4 + c4] = o;
        }
    }
}

// ---------------- FP16 tensor-core GEMM (BK=32, 3-stage, 2 CTAs/SM) ------------
#define HSTR 40

__device__ __forceinline__ void mma_f16(float* c, const unsigned* a, const unsigned* b) {
    asm("mma.sync.aligned.m16n8k16.row.col.f32.f16.f16.f32 "
        "{%0,%1,%2,%3}, {%4,%5,%6,%7}, {%8,%9}, {%0,%1,%2,%3};"
        : "+f"(c[0]), "+f"(c[1]), "+f"(c[2]), "+f"(c[3])
        : "r"(a[0]), "r"(a[1]), "r"(a[2]), "r"(a[3]), "r"(b[0]), "r"(b[1]));
}
__device__ __forceinline__ void ldsm4(unsigned* r, unsigned addr) {
    asm volatile("ldmatrix.sync.aligned.m8n8.x4.shared.b16 {%0,%1,%2,%3}, [%4];"
                 : "=r"(r[0]), "=r"(r[1]), "=r"(r[2]), "=r"(r[3]) : "r"(addr));
}
__device__ __forceinline__ void cp16(unsigned saddr, const void* g, bool ok) {
    int sz = ok ? 16 : 0;
    asm volatile("cp.async.cg.shared.global [%0], [%1], 16, %2;"
                 :: "r"(saddr), "l"(g), "r"(sz));
}
#define CP_COMMIT() asm volatile("cp.async.commit_group;")

template<bool CONCAT, bool EPI, bool HOUT>
__global__ __launch_bounds__(256, 2) void gemm_f16(
    const __half* __restrict__ A1, const __half* __restrict__ A2, int K1,
    const __half* __restrict__ Wt, void* __restrict__ Cv,
    const float* __restrict__ bias, int M, int N, int K)
{
    gdl();
    constexpr int S = 3;
    extern __shared__ __half sh[];
    __half* Asm = sh;
    __half* Bsm = sh + S * 128 * HSTR;

    const int tid = threadIdx.x;
    const int bm = blockIdx.y * 128;
    const int bn = blockIdx.x * 128;

    const int w = tid >> 5, lane = tid & 31;
    const int wm = (w & 3) * 32;
    const int wn = (w >> 2) * 64;
    const int lr = lane >> 2, lc = lane & 3;

    const int aRow = (lane & 7) + 8 * ((lane >> 3) & 1);
    const int aK   = 8 * (lane >> 4);
    const int bRow = (lane & 7) + 8 * (lane >> 4);
    const int bK   = 8 * ((lane >> 3) & 1);

    float acc[2][8][4];
#pragma unroll
    for (int mi = 0; mi < 2; mi++)
#pragma unroll
        for (int ni = 0; ni < 8; ni++)
#pragma unroll
            for (int q = 0; q < 4; q++) acc[mi][ni][q] = 0.f;

    const int K2 = K - K1;

    auto issue = [&](int kt) {
        int stage = kt % S;
        int kg = kt * 32;
        __half* As = Asm + stage * 128 * HSTR;
        __half* Bs = Bsm + stage * 128 * HSTR;
#pragma unroll
        for (int i = 0; i < 2; i++) {
            int chunk = tid + 256 * i;
            int rr = chunk >> 2, cc = chunk & 3;
            const __half* g;
            if (CONCAT) {
                g = (kg < K1) ? A1 + (size_t)(bm + rr) * K1 + kg + cc * 8
                              : A2 + (size_t)(bm + rr) * K2 + (kg - K1) + cc * 8;
            } else {
                g = A1 + (size_t)(bm + rr) * K + kg + cc * 8;
            }
            cp16(sm32(&As[rr * HSTR + cc * 8]), g, (bm + rr) < M);
        }
#pragma unroll
        for (int i = 0; i < 2; i++) {
            int chunk = tid + 256 * i;
            int rr = chunk >> 2, cc = chunk & 3;
            const __half* g = Wt + (size_t)(bn + rr) * K + kg + cc * 8;
            cp16(sm32(&Bs[rr * HSTR + cc * 8]), g, true);
        }
        CP_COMMIT();
    };

    gds();   // predecessor outputs (A operand, weights) now visible
    const int ktn = K / 32;
    issue(0);
    if (1 < ktn) issue(1);

    for (int t = 0; t < ktn; t++) {
        if (t + 1 < ktn) asm volatile("cp.async.wait_group %0;" :: "n"(1));
        else             asm volatile("cp.async.wait_group %0;" :: "n"(0));
        __syncthreads();
        const __half* Ab = Asm + (t % S) * 128 * HSTR;
        const __half* Bb = Bsm + (t % S) * 128 * HSTR;
#pragma unroll
        for (int kc = 0; kc < 32; kc += 16) {
            unsigned a[2][4];
#pragma unroll
            for (int mi = 0; mi < 2; mi++)
                ldsm4(a[mi], sm32(Ab + (wm + mi * 16 + aRow) * HSTR + kc + aK));
            unsigned b[8][2];
#pragma unroll
            for (int pj = 0; pj < 4; pj++) {
                unsigned r4[4];
                ldsm4(r4, sm32(Bb + (wn + pj * 16 + bRow) * HSTR + kc + bK));
                b[pj * 2][0] = r4[0]; b[pj * 2][1] = r4[1];
                b[pj * 2 + 1][0] = r4[2]; b[pj * 2 + 1][1] = r4[3];
            }
#pragma unroll
            for (int ni = 0; ni < 8; ni++) {
                mma_f16(acc[0][ni], a[0], b[ni]);
                mma_f16(acc[1][ni], a[1], b[ni]);
            }
        }
        if (t + 2 < ktn) issue(t + 2);
    }

#pragma unroll
    for (int mi = 0; mi < 2; mi++) {
#pragma unroll
        for (int ni = 0; ni < 8; ni++) {
            int r0 = bm + wm + mi * 16 + lr;
            int col = bn + wn + ni * 8 + 2 * lc;
            float2 v0 = make_float2(acc[mi][ni][0], acc[mi][ni][1]);
            float2 v1 = make_float2(acc[mi][ni][2], acc[mi][ni][3]);
            if (EPI) {
                float2 bb = *(const float2*)(bias + col);
                v0.x += bb.x; v0.y += bb.y;
                v1.x += bb.x; v1.y += bb.y;
                v0.x = v0.x > 0.f ? v0.x : SLOPE * v0.x;
                v0.y = v0.y > 0.f ? v0.y : SLOPE * v0.y;
                v1.x = v1.x > 0.f ? v1.x : SLOPE * v1.x;
                v1.y = v1.y > 0.f ? v1.y : SLOPE * v1.y;
            }
            if (HOUT) {
                __half* C = (__half*)Cv;
                if (r0 < M)     *(__half2*)(C + (size_t)r0 * N + col) = __float22half2_rn(v0);
                if (r0 + 8 < M) *(__half2*)(C + (size_t)(r0 + 8) * N + col) = __float22half2_rn(v1);
            } else {
                float* C = (float*)Cv;
                if (r0 < M)     *(float2*)(C + (size_t)r0 * N + col) = v0;
                if (r0 + 8 < M) *(float2*)(C + (size_t)(r0 + 8) * N + col) = v1;
            }
        }
    }
}

// ---------------- fused head (serial per-node; weight staging pre-wait) --------
__global__ __launch_bounds__(128) void head_kernel(
    const __half* __restrict__ h3,
    const float* __restrict__ Wp, const float* __restrict__ bp,
    const float* __restrict__ Wf1, const float* __restrict__ bf1,
    const float* __restrict__ Wf2, const float* __restrict__ bf2,
    float* __restrict__ out, int n)
{
    gdl();
    __shared__ float sWp[64 * 32], sWf1[32 * 32], sWf2[64], sbp[32], sbf1[32], sbf2[2];
    // weights are kernel inputs (not produced upstream) -> stage BEFORE the wait
    for (int i = threadIdx.x; i < 64 * 32; i += blockDim.x) sWp[i] = Wp[i];
    for (int i = threadIdx.x; i < 32 * 32; i += blockDim.x) sWf1[i] = Wf1[i];
    for (int i = threadIdx.x; i < 64; i += blockDim.x) sWf2[i] = Wf2[i];
    if (threadIdx.x < 32) { sbp[threadIdx.x] = bp[threadIdx.x]; sbf1[threadIdx.x] = bf1[threadIdx.x]; }
    if (threadIdx.x < 2) sbf2[threadIdx.x] = bf2[threadIdx.x];
    __syncthreads();
    gds();
    int nidx = blockIdx.x * blockDim.x + threadIdx.x;
    if (nidx >= n) return;

    float p[32];
#pragma unroll
    for (int j = 0; j < 32; j++) p[j] = sbp[j];
    const __half2* hx = (const __half2*)(h3 + (size_t)nidx * 64);
    for (int i2 = 0; i2 < 32; i2++) {
        float2 xf = __half22float2(hx[i2]);
#pragma unroll
        for (int j = 0; j < 32; j++) {
            p[j] = fmaf(xf.x, sWp[(2 * i2) * 32 + j], p[j]);
            p[j] = fmaf(xf.y, sWp[(2 * i2 + 1) * 32 + j], p[j]);
        }
    }
    float q[32];
#pragma unroll
    for (int j = 0; j < 32; j++) q[j] = sbf1[j];
#pragma unroll
    for (int i = 0; i < 32; i++) {
#pragma unroll
        for (int j = 0; j < 32; j++) q[j] = fmaf(p[i], sWf1[i * 32 + j], q[j]);
    }
#pragma unroll
    for (int j = 0; j < 32; j++) q[j] = q[j] > 0.f ? q[j] : SLOPE * q[j];
    float o0 = sbf2[0], o1 = sbf2[1];
#pragma unroll
    for (int i = 0; i < 32; i++) { o0 = fmaf(q[i], sWf2[i * 2], o0); o1 = fmaf(q[i], sWf2[i * 2 + 1], o1); }
    out[(size_t)nidx * 2]     = o0;
    out[(size_t)nidx * 2 + 1] = o1;
}

// ---------------- launch ------------------------------------------------------
static inline int cdiv(long long a, int b) { return (int)((a + b - 1) / b); }

template<typename K, typename... Args>
static void launch_pdl(K k, dim3 g, dim3 b, size_t smem, Args... args) {
    cudaLaunchConfig_t cfg = {};
    cfg.gridDim = g;
    cfg.blockDim = b;
    cfg.dynamicSmemBytes = smem;
    cfg.stream = 0;
    cudaLaunchAttribute at[1];
    at[0].id = cudaLaunchAttributeProgrammaticStreamSerialization;
    at[0].val.programmaticStreamSerializationAllowed = 1;
    cfg.attrs = at;
    cfg.numAttrs = 1;
    cudaLaunchKernelEx(&cfg, k, args...);
}

extern "C" void kernel_launch(void* const* d_in, const int* in_sizes, int n_in,
                              void* d_out, int out_size)
{
    const float* x   = (const float*)d_in[0];
    const int*   ei  = (const int*)d_in[1];
    // d_in[2..4] edge_attr/We/be: dead code in the reference
    const float* W1l = (const float*)d_in[5];
    const float* b1  = (const float*)d_in[6];
    const float* W1r = (const float*)d_in[7];
    const float* W2l = (const float*)d_in[8];
    const float* b2  = (const float*)d_in[9];
    const float* W2r = (const float*)d_in[10];
    const float* W3l = (const float*)d_in[11];
    const float* b3  = (const float*)d_in[12];
    const float* W3r = (const float*)d_in[13];
    const float* Wp  = (const float*)d_in[14];
    const float* bp  = (const float*)d_in[15];
    const float* Wf1 = (const float*)d_in[16];
    const float* bf1 = (const float*)d_in[17];
    const float* Wf2 = (const float*)d_in[18];
    const float* bf2 = (const float*)d_in[19];

    const int n  = in_sizes[0] / 128;   // 50000
    const int ne = in_sizes[1] / 2;     // 800000
    const int* src = ei;
    const int* dst = ei + ne;

    int *deg, *part, *rowptr, *cursor, *csr;
    __half *xh, *wt1h, *wt2h, *wt3h, *mean1h, *h1h, *c2h, *h2h, *c3h, *h3h;
    cudaGetSymbolAddress((void**)&deg,    g_deg);
    cudaGetSymbolAddress((void**)&part,   g_part);
    cudaGetSymbolAddress((void**)&rowptr, g_rowptr);
    cudaGetSymbolAddress((void**)&cursor, g_cursor);
    cudaGetSymbolAddress((void**)&csr,    g_csr);
    cudaGetSymbolAddress((void**)&xh,     g_xh);
    cudaGetSymbolAddress((void**)&wt1h,   g_wt1h);
    cudaGetSymbolAddress((void**)&wt2h,   g_wt2h);
    cudaGetSymbolAddress((void**)&wt3h,   g_wt3h);
    cudaGetSymbolAddress((void**)&mean1h, g_mean1h);
    cudaGetSymbolAddress((void**)&h1h,    g_h1h);
    cudaGetSymbolAddress((void**)&c2h,    g_c2h);
    cudaGetSymbolAddress((void**)&h2h,    g_h2h);
    cudaGetSymbolAddress((void**)&c3h,    g_c3h);
    cudaGetSymbolAddress((void**)&h3h,    g_h3h);
    float* out = (float*)d_out;

    const int T = 256;
    const int gM = cdiv(n, 128);   // 391
    const int NB = cdiv(n, 256);   // 196 scan blocks

    const int SMEM = 3 * (128 + 128) * HSTR * 2;   // 61440 B -> 2 CTAs/SM
    cudaFuncSetAttribute(gemm_f16<true, true, true>,
                         cudaFuncAttributeMaxDynamicSharedMemorySize, SMEM);
    cudaFuncSetAttribute(gemm_f16<false, false, true>,
                         cudaFuncAttributeMaxDynamicSharedMemorySize, SMEM);

    // ---- fused prologue: deg count + x->half + weight prep (normal launch)
    cudaMemsetAsync(deg, 0, (size_t)n * sizeof(int));
    const int CB = cdiv(cdiv(ne, 4), T);
    const int XB = cdiv((long long)n * 32, T);
    const int PB = cdiv(512 * 256 + 512 * 512 + 128 * 256, T);
    prologue_kernel<<<CB + XB + PB, T>>>(dst, deg, ne, x, n * 32,
                                         W1l, W1r, W2l, W2r, W3l, W3r, CB, XB);

    // ---- PDL chain: scan -> scatter -> layers -> head
    launch_pdl(scanA, dim3(NB), dim3(256), 0, (const int*)deg, part, n);
    launch_pdl(scanC, dim3(NB), dim3(256), 0,
               (const int*)deg, (const int*)part, rowptr, cursor, n, NB, ne);
    launch_pdl(scatter_kernel, dim3(cdiv(cdiv(ne, 4), T)), dim3(T), 0,
               src, dst, cursor, csr, ne);

    launch_pdl(csr_agg<32, false, true>, dim3(cdiv(n, 8)), dim3(T), 0,
               (const __half*)xh, 32, (const int*)rowptr, (const int*)csr,
               (const __half*)nullptr, 0, (const float*)nullptr,
               (void*)mean1h, 32, n);
    launch_pdl(gemm_f16<true, true, true>, dim3(4, gM), dim3(256), (size_t)SMEM,
               (const __half*)mean1h, (const __half*)xh, 128,
               (const __half*)wt1h, (void*)h1h, b1, n, 512, 256);

    launch_pdl(gemm_f16<false, false, true>, dim3(4, gM), dim3(256), (size_t)SMEM,
               (const __half*)h1h, (const __half*)nullptr, 0,
               (const __half*)wt2h, (void*)c2h, (const float*)nullptr, n, 512, 512);
    launch_pdl(csr_agg<64, true, true>, dim3(cdiv(n, 8)), dim3(T), 0,
               (const __half*)c2h, 128, (const int*)rowptr, (const int*)csr,
               (const __half*)(c2h + 256), 128, b2, (void*)h2h, 64, n);

    launch_pdl(gemm_f16<false, false, true>, dim3(1, gM), dim3(256), (size_t)SMEM,
               (const __half*)h2h, (const __half*)nullptr, 0,
               (const __half*)wt3h, (void*)c3h, (const float*)nullptr, n, 128, 256);
    launch_pdl(csr_agg<16, true, true>, dim3(cdiv(n, 16)), dim3(T), 0,
               (const __half*)c3h, 32, (const int*)rowptr, (const int*)csr,
               (const __half*)(c3h + 64), 32, b3, (void*)h3h, 16, n);

    launch_pdl(head_kernel, dim3(cdiv(n, 128)), dim3(128), 0,
               (const __half*)h3h, Wp, bp, Wf1, bf1, Wf2, bf2, out, n);
}